// round 16
// baseline (speedup 1.0000x reference)
#include <cuda_runtime.h>
#include <cuda_bf16.h>
#include <cstdint>

// Problem constants
#define BATCH 2
#define SEQ   2048
#define EMB   1024
#define NHEAD 16
#define HS    64
#define MROWS (BATCH * SEQ)          // 4096
#define NBIG  1152                   // 1024 (q) + 128 (kv)

// ---------------------------------------------------------------------------
// Scratch (static device globals — no allocation)
// ---------------------------------------------------------------------------
__device__ __nv_bfloat16 g_xhi [MROWS * EMB];
__device__ __nv_bfloat16 g_xlo [MROWS * EMB];
__device__ __nv_bfloat16 g_qhi [MROWS * EMB];
__device__ __nv_bfloat16 g_qlo [MROWS * EMB];
__device__ __nv_bfloat16 g_yhi [MROWS * EMB];
__device__ __nv_bfloat16 g_ylo [MROWS * EMB];
__device__ __nv_bfloat16 g_wbhi[NBIG * EMB];     // [Wq; Wk; Wv] rows
__device__ __nv_bfloat16 g_wblo[NBIG * EMB];
__device__ __nv_bfloat16 g_wphi[EMB * EMB];
__device__ __nv_bfloat16 g_wplo[EMB * EMB];
__device__ __nv_bfloat16 g_kvhi[MROWS * 128];
__device__ __nv_bfloat16 g_kvlo[MROWS * 128];

// ---------------------------------------------------------------------------
// Target-agnostic primitives (valid at .target sm_103)
// ---------------------------------------------------------------------------
__device__ __forceinline__ uint32_t smem_u32(const void* p) {
    uint32_t a;
    asm("{ .reg .u64 t; cvta.to.shared.u64 t, %1; cvt.u32.u64 %0, t; }" : "=r"(a) : "l"(p));
    return a;
}
__device__ __forceinline__ void ldsm_x4(uint32_t& r0, uint32_t& r1,
                                        uint32_t& r2, uint32_t& r3, uint32_t addr)
{
    asm volatile("ldmatrix.sync.aligned.m8n8.x4.shared.b16 {%0,%1,%2,%3}, [%4];"
                 : "=r"(r0), "=r"(r1), "=r"(r2), "=r"(r3) : "r"(addr));
}
__device__ __forceinline__ void ldsm_x4_t(uint32_t& r0, uint32_t& r1,
                                          uint32_t& r2, uint32_t& r3, uint32_t addr)
{
    asm volatile("ldmatrix.sync.aligned.m8n8.x4.trans.shared.b16 {%0,%1,%2,%3}, [%4];"
                 : "=r"(r0), "=r"(r1), "=r"(r2), "=r"(r3) : "r"(addr));
}
__device__ __forceinline__ void mma16816(float* d, const uint32_t* a, const uint32_t* b)
{
    asm volatile("mma.sync.aligned.m16n8k16.row.col.f32.bf16.bf16.f32 "
                 "{%0,%1,%2,%3}, {%4,%5,%6,%7}, {%8,%9}, {%0,%1,%2,%3};"
                 : "+f"(d[0]), "+f"(d[1]), "+f"(d[2]), "+f"(d[3])
                 : "r"(a[0]), "r"(a[1]), "r"(a[2]), "r"(a[3]), "r"(b[0]), "r"(b[1]));
}
__device__ __forceinline__ void cp_async16(uint32_t saddr, const void* gptr) {
    asm volatile("cp.async.cg.shared.global [%0], [%1], 16;" :: "r"(saddr), "l"(gptr));
}
#define CP_COMMIT() asm volatile("cp.async.commit_group;" ::: "memory")
#define CP_WAIT1()  asm volatile("cp.async.wait_group 1;" ::: "memory")

// exp2 on the FMA pipe (no MUFU). Valid for y <= ~1; clamps below -100.
__device__ __forceinline__ float exp2_fast(float y) {
    y = fmaxf(y, -100.f);
    float z = y + 12582912.f;
    int   n = __float_as_int(z) - 0x4B400000;
    float f = y - (z - 12582912.f);
    float p =             1.3333558e-3f;
    p = fmaf(p, f, 9.6181291e-3f);
    p = fmaf(p, f, 5.5504109e-2f);
    p = fmaf(p, f, 2.4022651e-1f);
    p = fmaf(p, f, 6.9314718e-1f);
    p = fmaf(p, f, 1.0f);
    return p * __int_as_float((n + 127) << 23);
}
__device__ __forceinline__ uint32_t pack_bf16(float x, float y) {
    __nv_bfloat162 t = __floats2bfloat162_rn(x, y);
    return *(uint32_t*)&t;
}
__device__ __forceinline__ uint32_t pack_bf16_res(float x, float y, uint32_t hi) {
    __nv_bfloat162 h = *(__nv_bfloat162*)&hi;
    return pack_bf16(x - __bfloat162float(h.x), y - __bfloat162float(h.y));
}

// ---------------------------------------------------------------------------
// ONE fused split kernel: x -> xhi/xlo, Wp -> wphi/wplo, [Wq;Wk;Wv] -> wbhi/wblo
// ---------------------------------------------------------------------------
__device__ __forceinline__ void split4_store(float4 v,
                                             __nv_bfloat16* hi, __nv_bfloat16* lo,
                                             int i4)
{
    __nv_bfloat16 h0 = __float2bfloat16(v.x), h1 = __float2bfloat16(v.y);
    __nv_bfloat16 h2 = __float2bfloat16(v.z), h3 = __float2bfloat16(v.w);
    __nv_bfloat16 l0 = __float2bfloat16(v.x - __bfloat162float(h0));
    __nv_bfloat16 l1 = __float2bfloat16(v.y - __bfloat162float(h1));
    __nv_bfloat16 l2 = __float2bfloat16(v.z - __bfloat162float(h2));
    __nv_bfloat16 l3 = __float2bfloat16(v.w - __bfloat162float(h3));
    ((__nv_bfloat162*)hi)[2 * i4]     = __nv_bfloat162(h0, h1);
    ((__nv_bfloat162*)hi)[2 * i4 + 1] = __nv_bfloat162(h2, h3);
    ((__nv_bfloat162*)lo)[2 * i4]     = __nv_bfloat162(l0, l1);
    ((__nv_bfloat162*)lo)[2 * i4 + 1] = __nv_bfloat162(l2, l3);
}

#define SPLIT_N1 (MROWS * EMB / 4)   // 1048576 x-float4s
#define SPLIT_N2 (EMB * EMB / 4)     //  262144 Wp-float4s
#define SPLIT_N3 (NBIG * EMB / 4)    //  294912 wbig-float4s
#define SPLIT_TOT (SPLIT_N1 + SPLIT_N2 + SPLIT_N3)

__global__ void split_all(const float* __restrict__ x,
                          const float* __restrict__ Wq,
                          const float* __restrict__ Wk,
                          const float* __restrict__ Wv,
                          const float* __restrict__ Wp)
{
    int i = blockIdx.x * blockDim.x + threadIdx.x;
    if (i < SPLIT_N1) {
        split4_store(((const float4*)x)[i], g_xhi, g_xlo, i);
    } else if (i < SPLIT_N1 + SPLIT_N2) {
        int k = i - SPLIT_N1;
        split4_store(((const float4*)Wp)[k], g_wphi, g_wplo, k);
    } else if (i < SPLIT_TOT) {
        int k = i - SPLIT_N1 - SPLIT_N2;          // wbig float4 index
        int j = (4 * k) >> 10, c = (4 * k) & 1023;
        const float* src;
        if (j < 1024)      src = Wq + (size_t)j * EMB + c;
        else if (j < 1088) src = Wk + (size_t)(j - 1024) * EMB + c;
        else               src = Wv + (size_t)(j - 1088) * EMB + c;
        split4_store(*(const float4*)src, g_wbhi, g_wblo, k);
    }
}

// ---------------------------------------------------------------------------
// hi/lo-aware bf16 split GEMM on mma.sync (round-12, passing at 366.7 total).
// ---------------------------------------------------------------------------
#define NITER  32            // 32 chunks of K=32
#define MATB2  8192          // 128 rows * 64B
#define STAGEB (4 * MATB2)   // Ahi+Alo+Bhi+Blo = 32768
#define GSMEM  (3 * STAGEB)  // 98304

__global__ __launch_bounds__(256, 2)
void gemm3_mma(const __nv_bfloat16* __restrict__ Ahi, const __nv_bfloat16* __restrict__ Alo,
               const __nv_bfloat16* __restrict__ Bhi, const __nv_bfloat16* __restrict__ Blo,
               const float* __restrict__ bias, float* __restrict__ Cf,
               __nv_bfloat16* __restrict__ Chi, __nv_bfloat16* __restrict__ Clo, int ldc,
               __nv_bfloat16* __restrict__ Chi2, __nv_bfloat16* __restrict__ Clo2)
{
    extern __shared__ __align__(16) char sm[];

    const int tid  = threadIdx.x;
    const int wid  = tid >> 5;
    const int lane = tid & 31;
    const int m0 = blockIdx.y * 128;
    const int n0 = blockIdx.x * 128;
    const int wm = (wid & 1) << 6;
    const int wn = (wid >> 1) << 5;

    const int lt = lane >> 3;
    const int lr = lane & 7;
    const int rA = wm + lr + ((lt & 1) << 3);
    const int rB = wn + lr + ((lt >> 1) << 3);
    const uint32_t rowA = (uint32_t)rA * 64;
    const uint32_t rowB = (uint32_t)rB * 64;
    const int rxA = (rA >> 1) & 3;
    const int rxB = (rB >> 1) & 3;
    const int sA  = lt >> 1;
    const int sB  = lt & 1;
    const uint32_t sbase = smem_u32(sm);

    const int lrw0 = tid >> 2,          lsg0 = tid & 3;
    const int lrw1 = (tid + 256) >> 2,  lsg1 = (tid + 256) & 3;
    const uint32_t ldst0 = (uint32_t)lrw0 * 64 + (uint32_t)((lsg0 ^ ((lrw0 >> 1) & 3)) << 4);
    const uint32_t ldst1 = (uint32_t)lrw1 * 64 + (uint32_t)((lsg1 ^ ((lrw1 >> 1) & 3)) << 4);

    float d[4][4][4];
#pragma unroll
    for (int mi = 0; mi < 4; mi++)
#pragma unroll
        for (int ni = 0; ni < 4; ni++)
#pragma unroll
            for (int q = 0; q < 4; q++) d[mi][ni][q] = 0.f;

#define LOAD_STAGE(bufi, ci) do {                                                  \
    const int _k0 = (ci) << 5;                                                     \
    const uint32_t _sb = sbase + (uint32_t)(bufi) * STAGEB;                        \
    cp_async16(_sb + ldst0,             Ahi + (size_t)(m0 + lrw0) * EMB + _k0 + lsg0 * 8); \
    cp_async16(_sb + ldst1,             Ahi + (size_t)(m0 + lrw1) * EMB + _k0 + lsg1 * 8); \
    cp_async16(_sb + MATB2 + ldst0,     Alo + (size_t)(m0 + lrw0) * EMB + _k0 + lsg0 * 8); \
    cp_async16(_sb + MATB2 + ldst1,     Alo + (size_t)(m0 + lrw1) * EMB + _k0 + lsg1 * 8); \
    cp_async16(_sb + 2 * MATB2 + ldst0, Bhi + (size_t)(n0 + lrw0) * EMB + _k0 + lsg0 * 8); \
    cp_async16(_sb + 2 * MATB2 + ldst1, Bhi + (size_t)(n0 + lrw1) * EMB + _k0 + lsg1 * 8); \
    cp_async16(_sb + 3 * MATB2 + ldst0, Blo + (size_t)(n0 + lrw0) * EMB + _k0 + lsg0 * 8); \
    cp_async16(_sb + 3 * MATB2 + ldst1, Blo + (size_t)(n0 + lrw1) * EMB + _k0 + lsg1 * 8); \
} while (0)

    LOAD_STAGE(0, 0); CP_COMMIT();
    LOAD_STAGE(1, 1); CP_COMMIT();

    int buf = 0;
    for (int c = 0; c < NITER; c++) {
        CP_WAIT1();
        __syncthreads();

        if (c + 2 < NITER) LOAD_STAGE((buf + 2) % 3, c + 2);
        CP_COMMIT();

        const uint32_t stb = sbase + (uint32_t)buf * STAGEB;
#pragma unroll
        for (int ks = 0; ks < 2; ks++) {
            const uint32_t aoffk = (uint32_t)(((2 * ks + sA) ^ rxA) << 4);
            const uint32_t boffk = (uint32_t)(((2 * ks + sB) ^ rxB) << 4);

            uint32_t ah[4][4], bh[2][4];
#pragma unroll
            for (int mi = 0; mi < 4; mi++)
                ldsm_x4(ah[mi][0], ah[mi][1], ah[mi][2], ah[mi][3],
                        stb + rowA + (uint32_t)mi * 1024 + aoffk);
#pragma unroll
            for (int nt = 0; nt < 2; nt++)
                ldsm_x4(bh[nt][0], bh[nt][1], bh[nt][2], bh[nt][3],
                        stb + 2 * MATB2 + rowB + (uint32_t)nt * 1024 + boffk);
#pragma unroll
            for (int mi = 0; mi < 4; mi++)
#pragma unroll
                for (int ni = 0; ni < 4; ni++)
                    mma16816(d[mi][ni], ah[mi], &bh[ni >> 1][(ni & 1) * 2]);

            uint32_t bl[2][4];
#pragma unroll
            for (int nt = 0; nt < 2; nt++)
                ldsm_x4(bl[nt][0], bl[nt][1], bl[nt][2], bl[nt][3],
                        stb + 3 * MATB2 + rowB + (uint32_t)nt * 1024 + boffk);
#pragma unroll
            for (int mi = 0; mi < 4; mi++)
#pragma unroll
                for (int ni = 0; ni < 4; ni++)
                    mma16816(d[mi][ni], ah[mi], &bl[ni >> 1][(ni & 1) * 2]);

            uint32_t al[4][4];
#pragma unroll
            for (int mi = 0; mi < 4; mi++)
                ldsm_x4(al[mi][0], al[mi][1], al[mi][2], al[mi][3],
                        stb + MATB2 + rowA + (uint32_t)mi * 1024 + aoffk);
#pragma unroll
            for (int mi = 0; mi < 4; mi++)
#pragma unroll
                for (int ni = 0; ni < 4; ni++)
                    mma16816(d[mi][ni], al[mi], &bh[ni >> 1][(ni & 1) * 2]);
        }
        buf = (buf + 1) % 3;
    }

    __nv_bfloat16* Hi = Chi;
    __nv_bfloat16* Lo = Clo;
    int ld = ldc, cbase = 0;
    if (Chi2 && n0 >= 1024) { Hi = Chi2; Lo = Clo2; ld = 128; cbase = 1024; }

    const int erow = lane >> 2;
    const int ecol = (lane & 3) << 1;
#pragma unroll
    for (int mi = 0; mi < 4; mi++) {
#pragma unroll
        for (int ni = 0; ni < 4; ni++) {
            const int r = m0 + wm + mi * 16 + erow;
            const int cc = n0 + wn + ni * 8 + ecol;
            if (Cf) {
                float bx = 0.f, by = 0.f;
                if (bias) { bx = bias[cc]; by = bias[cc + 1]; }
                *(float2*)(Cf + (size_t)r * ldc + cc) =
                    make_float2(d[mi][ni][0] + bx, d[mi][ni][1] + by);
                *(float2*)(Cf + (size_t)(r + 8) * ldc + cc) =
                    make_float2(d[mi][ni][2] + bx, d[mi][ni][3] + by);
            } else {
                const int co = cc - cbase;
                uint32_t h0 = pack_bf16(d[mi][ni][0], d[mi][ni][1]);
                uint32_t h1 = pack_bf16(d[mi][ni][2], d[mi][ni][3]);
                *(uint32_t*)(Hi + (size_t)r * ld + co) = h0;
                *(uint32_t*)(Hi + (size_t)(r + 8) * ld + co) = h1;
                *(uint32_t*)(Lo + (size_t)r * ld + co) =
                    pack_bf16_res(d[mi][ni][0], d[mi][ni][1], h0);
                *(uint32_t*)(Lo + (size_t)(r + 8) * ld + co) =
                    pack_bf16_res(d[mi][ni][2], d[mi][ni][3], h1);
            }
        }
    }
#undef LOAD_STAGE
}

// ---------------------------------------------------------------------------
// Tensor-core causal MQA flash attention — round-13 shape (366.7 µs total),
// reverted verbatim: packed 128B rows + SW128 swizzle, 2 CTAs/SM, k-major S
// with Q fragments re-loaded from smem each tile (NO register hoisting — both
// hoist variants spilled past the 256-reg budget and regressed).
// smem: qhi @0 (16384), qlo @16384 | stages @32768, 32768 each:
//       khi@0, klo@8192, vhi@16384, vlo@24576
// ---------------------------------------------------------------------------
#define SM_QLO2 16384
#define SM_KV2  32768
#define STG2    32768
#define ATT_SMEM (SM_KV2 + 2 * STG2)   // 98304

__global__ __launch_bounds__(128, 2)
void mqa_attn_mma(const __nv_bfloat16* __restrict__ qhi,
                  const __nv_bfloat16* __restrict__ qlo,
                  const __nv_bfloat16* __restrict__ kvhi,
                  const __nv_bfloat16* __restrict__ kvlo,
                  __nv_bfloat16* __restrict__ yhi,
                  __nv_bfloat16* __restrict__ ylo)
{
    extern __shared__ __align__(16) char sm[];
    const int qt   = (int)gridDim.x - 1 - (int)blockIdx.x;  // big tiles first
    const int h    = blockIdx.y;
    const int b    = blockIdx.z;
    const int tid  = threadIdx.x;
    const int w    = tid >> 5;
    const int lane = tid & 31;
    const uint32_t sbase = smem_u32(sm);

    const int lt = lane >> 3;
    const int lr = lane & 7;
    const uint32_t qrow = (uint32_t)(32 * w + lr + ((lt & 1) << 3)) * 128;  // + mi*2048
    const int sQ = lt >> 1;
    const uint32_t krow = (uint32_t)(lr + ((lt >> 1) << 3)) * 128;          // + n2*2048
    const int sK = lt & 1;
    const uint32_t vrow = (uint32_t)(lr + ((lt & 1) << 3)) * 128;           // + ks*2048
    const int sV = lt >> 1;

    // ---- load Q tile (contiguous 8 q_raw rows = [128,64]) into smem hi/lo ----
    {
        size_t qoff = ((size_t)b * SEQ + (size_t)(h * 128 + qt * 8)) * EMB;
        const uint4* sh = (const uint4*)(qhi + qoff);
        const uint4* sl = (const uint4*)(qlo + qoff);
#pragma unroll
        for (int i = 0; i < 8; i++) {
            int c = tid + i * 128;          // 0..1023 chunks of 16B
            int r = c >> 3, sg = c & 7;
            uint32_t dst = (uint32_t)r * 128 + (uint32_t)((sg ^ (r & 7)) << 4);
            *(uint4*)(sm + dst)            = sh[c];
            *(uint4*)(sm + SM_QLO2 + dst)  = sl[c];
        }
    }

#define LOAD_KV(bufi, s) do {                                                      \
    size_t _rb = ((size_t)b * SEQ + (size_t)(s) * 64) * 128;                       \
    const char* _sh = (const char*)(kvhi + _rb);                                   \
    const char* _sl = (const char*)(kvlo + _rb);                                   \
    uint32_t _sb = sbase + SM_KV2 + (uint32_t)(bufi) * STG2;                       \
    _Pragma("unroll")                                                              \
    for (int _i = 0; _i < 8; _i++) {                                               \
        int _c = tid + _i * 128;                                                   \
        int _r = _c >> 4, _sg = _c & 15;                                           \
        uint32_t _dst = ((_sg < 8) ? 0u : 16384u)                                  \
                      + (uint32_t)_r * 128                                         \
                      + (uint32_t)((( _sg & 7) ^ (_r & 7)) << 4);                  \
        cp_async16(_sb + _dst,         _sh + _r * 256 + _sg * 16);                 \
        cp_async16(_sb + _dst + 8192,  _sl + _r * 256 + _sg * 16);                 \
    }                                                                              \
} while (0)

    float O[2][8][4];
#pragma unroll
    for (int mi = 0; mi < 2; mi++)
#pragma unroll
        for (int nt = 0; nt < 8; nt++)
#pragma unroll
            for (int q = 0; q < 4; q++) O[mi][nt][q] = 0.f;
    float mrow[2][2] = {{-1e30f, -1e30f}, {-1e30f, -1e30f}};
    float lrow[2][2] = {{0.f, 0.f}, {0.f, 0.f}};

    const float QSC = 0.125f * 1.44269504088896340736f;
    const int ntl = 2 * qt + 2;

    LOAD_KV(0, 0); CP_COMMIT();

    for (int s = 0; s < ntl; s++) {
        __syncthreads();                       // everyone done reading buf (s+1)&1
        if (s + 1 < ntl) LOAD_KV((s + 1) & 1, s + 1);
        CP_COMMIT();
        CP_WAIT1();                            // stage s complete
        __syncthreads();

        const uint32_t kb = sbase + SM_KV2 + (uint32_t)(s & 1) * STG2;

        // ---- S = Qhi@Khi + Qhi@Klo + Qlo@Khi (k-major, fragment reuse) ----
        float S[2][8][4];
#pragma unroll
        for (int mi = 0; mi < 2; mi++)
#pragma unroll
            for (int nt = 0; nt < 8; nt++)
#pragma unroll
                for (int q = 0; q < 4; q++) S[mi][nt][q] = 0.f;

#pragma unroll
        for (int ks = 0; ks < 4; ks++) {
            const uint32_t qoffk = (uint32_t)(((2 * ks + sQ) ^ lr) << 4);
            const uint32_t koffk = (uint32_t)(((2 * ks + sK) ^ lr) << 4);

            uint32_t qh[2][4], kh[4][4];
#pragma unroll
            for (int mi = 0; mi < 2; mi++)
                ldsm_x4(qh[mi][0], qh[mi][1], qh[mi][2], qh[mi][3],
                        sbase + qrow + (uint32_t)mi * 2048 + qoffk);
#pragma unroll
            for (int n2 = 0; n2 < 4; n2++)
                ldsm_x4(kh[n2][0], kh[n2][1], kh[n2][2], kh[n2][3],
                        kb + krow + (uint32_t)n2 * 2048 + koffk);
#pragma unroll
            for (int mi = 0; mi < 2; mi++)
#pragma unroll
                for (int nt = 0; nt < 8; nt++)
                    mma16816(S[mi][nt], qh[mi], &kh[nt >> 1][(nt & 1) * 2]);

            uint32_t kl[4][4];
#pragma unroll
            for (int n2 = 0; n2 < 4; n2++)
                ldsm_x4(kl[n2][0], kl[n2][1], kl[n2][2], kl[n2][3],
                        kb + 8192u + krow + (uint32_t)n2 * 2048 + koffk);
#pragma unroll
            for (int mi = 0; mi < 2; mi++)
#pragma unroll
                for (int nt = 0; nt < 8; nt++)
                    mma16816(S[mi][nt], qh[mi], &kl[nt >> 1][(nt & 1) * 2]);

            uint32_t ql[2][4];
#pragma unroll
            for (int mi = 0; mi < 2; mi++)
                ldsm_x4(ql[mi][0], ql[mi][1], ql[mi][2], ql[mi][3],
                        sbase + SM_QLO2 + qrow + (uint32_t)mi * 2048 + qoffk);
#pragma unroll
            for (int mi = 0; mi < 2; mi++)
#pragma unroll
                for (int nt = 0; nt < 8; nt++)
                    mma16816(S[mi][nt], ql[mi], &kh[nt >> 1][(nt & 1) * 2]);
        }

        // ---- mask (diagonal tiles only) + scale ----
        if (s >= 2 * qt) {
#pragma unroll
            for (int mi = 0; mi < 2; mi++) {
                const int r0 = qt * 128 + 32 * w + 16 * mi + (lane >> 2);
#pragma unroll
                for (int nt = 0; nt < 8; nt++) {
                    const int jb = s * 64 + nt * 8 + 2 * (lane & 3);
                    if (jb     > r0)     S[mi][nt][0] = -1e30f;
                    if (jb + 1 > r0)     S[mi][nt][1] = -1e30f;
                    if (jb     > r0 + 8) S[mi][nt][2] = -1e30f;
                    if (jb + 1 > r0 + 8) S[mi][nt][3] = -1e30f;
                }
            }
        }
#pragma unroll
        for (int mi = 0; mi < 2; mi++)
#pragma unroll
            for (int nt = 0; nt < 8; nt++)
#pragma unroll
                for (int q = 0; q < 4; q++) S[mi][nt][q] *= QSC;

        // ---- online softmax on fragments ----
        uint32_t phi[2][4][4], plo[2][4][4];
#pragma unroll
        for (int mi = 0; mi < 2; mi++) {
            float t0 = -1e30f, t1 = -1e30f;
#pragma unroll
            for (int nt = 0; nt < 8; nt++) {
                t0 = fmaxf(t0, fmaxf(S[mi][nt][0], S[mi][nt][1]));
                t1 = fmaxf(t1, fmaxf(S[mi][nt][2], S[mi][nt][3]));
            }
            t0 = fmaxf(t0, __shfl_xor_sync(0xffffffffu, t0, 1));
            t0 = fmaxf(t0, __shfl_xor_sync(0xffffffffu, t0, 2));
            t1 = fmaxf(t1, __shfl_xor_sync(0xffffffffu, t1, 1));
            t1 = fmaxf(t1, __shfl_xor_sync(0xffffffffu, t1, 2));
            const float m0n = fmaxf(mrow[mi][0], t0);
            const float m1n = fmaxf(mrow[mi][1], t1);
            const float c0 = exp2_fast(mrow[mi][0] - m0n);
            const float c1 = exp2_fast(mrow[mi][1] - m1n);
            mrow[mi][0] = m0n; mrow[mi][1] = m1n;
            lrow[mi][0] *= c0; lrow[mi][1] *= c1;
#pragma unroll
            for (int nt = 0; nt < 8; nt++) {
                O[mi][nt][0] *= c0; O[mi][nt][1] *= c0;
                O[mi][nt][2] *= c1; O[mi][nt][3] *= c1;
            }
            float ps0 = 0.f, ps1 = 0.f;
#pragma unroll
            for (int nt = 0; nt < 8; nt++) {
                float p0 = exp2_fast(S[mi][nt][0] - m0n);
                float p1 = exp2_fast(S[mi][nt][1] - m0n);
                float p2 = exp2_fast(S[mi][nt][2] - m1n);
                float p3 = exp2_fast(S[mi][nt][3] - m1n);
                ps0 += p0 + p1; ps1 += p2 + p3;
                S[mi][nt][0] = p0; S[mi][nt][1] = p1;
                S[mi][nt][2] = p2; S[mi][nt][3] = p3;
            }
            lrow[mi][0] += ps0; lrow[mi][1] += ps1;
            // pack P -> bf16 hi/lo A-fragments (C layout == A layout)
#pragma unroll
            for (int ks = 0; ks < 4; ks++) {
                phi[mi][ks][0] = pack_bf16(S[mi][2*ks][0],   S[mi][2*ks][1]);
                phi[mi][ks][1] = pack_bf16(S[mi][2*ks][2],   S[mi][2*ks][3]);
                phi[mi][ks][2] = pack_bf16(S[mi][2*ks+1][0], S[mi][2*ks+1][1]);
                phi[mi][ks][3] = pack_bf16(S[mi][2*ks+1][2], S[mi][2*ks+1][3]);
                plo[mi][ks][0] = pack_bf16_res(S[mi][2*ks][0],   S[mi][2*ks][1],   phi[mi][ks][0]);
                plo[mi][ks][1] = pack_bf16_res(S[mi][2*ks][2],   S[mi][2*ks][3],   phi[mi][ks][1]);
                plo[mi][ks][2] = pack_bf16_res(S[mi][2*ks+1][0], S[mi][2*ks+1][1], phi[mi][ks][2]);
                plo[mi][ks][3] = pack_bf16_res(S[mi][2*ks+1][2], S[mi][2*ks+1][3], phi[mi][ks][3]);
            }
        }

        // ---- O += Phi@Vhi + Plo@Vhi + Phi@Vlo (fragment reuse) ----
#pragma unroll
        for (int ks = 0; ks < 4; ks++) {
            const uint32_t vrb = vrow + (uint32_t)ks * 2048;
            uint32_t vh[4][4];
#pragma unroll
            for (int ng = 0; ng < 4; ng++)
                ldsm_x4_t(vh[ng][0], vh[ng][1], vh[ng][2], vh[ng][3],
                          kb + 16384u + vrb + (uint32_t)(((2 * ng + sV) ^ lr) << 4));
#pragma unroll
            for (int mi = 0; mi < 2; mi++)
#pragma unroll
                for (int nt = 0; nt < 8; nt++) {
                    const uint32_t* bb = &vh[nt >> 1][(nt & 1) * 2];
                    mma16816(O[mi][nt], phi[mi][ks], bb);
                    mma16816(O[mi][nt], plo[mi][ks], bb);
                }
            uint32_t vl[4][4];
#pragma unroll
            for (int ng = 0; ng < 4; ng++)
                ldsm_x4_t(vl[ng][0], vl[ng][1], vl[ng][2], vl[ng][3],
                          kb + 24576u + vrb + (uint32_t)(((2 * ng + sV) ^ lr) << 4));
#pragma unroll
            for (int mi = 0; mi < 2; mi++)
#pragma unroll
                for (int nt = 0; nt < 8; nt++)
                    mma16816(O[mi][nt], phi[mi][ks], &vl[nt >> 1][(nt & 1) * 2]);
        }
    }

    // ---- finalize: quad-reduce l, normalize, store bf16 hi/lo ----
#pragma unroll
    for (int mi = 0; mi < 2; mi++) {
        float l0 = lrow[mi][0], l1 = lrow[mi][1];
        l0 += __shfl_xor_sync(0xffffffffu, l0, 1);
        l0 += __shfl_xor_sync(0xffffffffu, l0, 2);
        l1 += __shfl_xor_sync(0xffffffffu, l1, 1);
        l1 += __shfl_xor_sync(0xffffffffu, l1, 2);
        const float i0 = 1.f / l0, i1 = 1.f / l1;
        const int r0 = qt * 128 + 32 * w + 16 * mi + (lane >> 2);
#pragma unroll
        for (int nt = 0; nt < 8; nt++) {
            const int col = h * HS + nt * 8 + 2 * (lane & 3);
            const size_t i0x = ((size_t)b * SEQ + r0) * EMB + col;
            const size_t i1x = ((size_t)b * SEQ + r0 + 8) * EMB + col;
            float v0 = O[mi][nt][0] * i0, v1 = O[mi][nt][1] * i0;
            float v2 = O[mi][nt][2] * i1, v3 = O[mi][nt][3] * i1;
            uint32_t ph0 = pack_bf16(v0, v1), ph1 = pack_bf16(v2, v3);
            *(uint32_t*)(yhi + i0x) = ph0;
            *(uint32_t*)(yhi + i1x) = ph1;
            *(uint32_t*)(ylo + i0x) = pack_bf16_res(v0, v1, ph0);
            *(uint32_t*)(ylo + i1x) = pack_bf16_res(v2, v3, ph1);
        }
    }
#undef LOAD_KV
}

// ---------------------------------------------------------------------------
extern "C" void kernel_launch(void* const* d_in, const int* in_sizes, int n_in,
                              void* d_out, int out_size)
{
    const float* x  = (const float*)d_in[0];
    const float* Wk = (const float*)d_in[1];
    const float* Wv = (const float*)d_in[2];
    const float* Wq = (const float*)d_in[3];
    const float* Wp = (const float*)d_in[4];
    const float* bp = (const float*)d_in[5];
    float* out = (float*)d_out;

    __nv_bfloat16 *xhi, *xlo, *qhi, *qlo, *yhi, *ylo;
    __nv_bfloat16 *wbhi, *wblo, *wphi, *wplo, *kvhi, *kvlo;
    cudaGetSymbolAddress((void**)&xhi, g_xhi);   cudaGetSymbolAddress((void**)&xlo, g_xlo);
    cudaGetSymbolAddress((void**)&qhi, g_qhi);   cudaGetSymbolAddress((void**)&qlo, g_qlo);
    cudaGetSymbolAddress((void**)&yhi, g_yhi);   cudaGetSymbolAddress((void**)&ylo, g_ylo);
    cudaGetSymbolAddress((void**)&wbhi, g_wbhi); cudaGetSymbolAddress((void**)&wblo, g_wblo);
    cudaGetSymbolAddress((void**)&wphi, g_wphi); cudaGetSymbolAddress((void**)&wplo, g_wplo);
    cudaGetSymbolAddress((void**)&kvhi, g_kvhi); cudaGetSymbolAddress((void**)&kvlo, g_kvlo);

    cudaFuncSetAttribute(gemm3_mma, cudaFuncAttributeMaxDynamicSharedMemorySize, GSMEM);
    cudaFuncSetAttribute(mqa_attn_mma, cudaFuncAttributeMaxDynamicSharedMemorySize, ATT_SMEM);

    // ONE fused precision-split launch (x, Wp, [Wq;Wk;Wv])
    split_all<<<(SPLIT_TOT + 255) / 256, 256>>>(x, Wq, Wk, Wv, Wp);

    // [q | kv] = x @ [Wq;Wk;Wv]^T -> q bf16 hi/lo [4096,1024] + kv hi/lo [4096,128]
    gemm3_mma<<<dim3(NBIG / 128, MROWS / 128), 256, GSMEM>>>(
        xhi, xlo, wbhi, wblo, nullptr, nullptr,
        qhi, qlo, EMB, kvhi, kvlo);

    // tensor-core flash attention (1 head/block, 512 blocks, 2 CTA/SM) -> y hi/lo
    mqa_attn_mma<<<dim3(SEQ / 128, NHEAD, BATCH), 128, ATT_SMEM>>>(
        qhi, qlo, kvhi, kvlo, yhi, ylo);

    // out = y @ Wp^T + bp (fp32 out)
    gemm3_mma<<<dim3(EMB / 128, MROWS / 128), 256, GSMEM>>>(
        yhi, ylo, wphi, wplo, bp, out, nullptr, nullptr, EMB,
        nullptr, nullptr);
}

// round 17
// speedup vs baseline: 1.5394x; 1.5394x over previous
#include <cuda_runtime.h>
#include <cuda_bf16.h>
#include <cstdint>

// Problem constants
#define BATCH 2
#define SEQ   2048
#define EMB   1024
#define NHEAD 16
#define HS    64
#define MROWS (BATCH * SEQ)          // 4096
#define NBIG  1152                   // 1024 (q) + 128 (kv)

// ---------------------------------------------------------------------------
// Scratch (static device globals — no allocation)
// ---------------------------------------------------------------------------
__device__ __nv_bfloat16 g_xhi [MROWS * EMB];
__device__ __nv_bfloat16 g_xlo [MROWS * EMB];
__device__ __nv_bfloat16 g_qhi [MROWS * EMB];
__device__ __nv_bfloat16 g_qlo [MROWS * EMB];
__device__ __nv_bfloat16 g_yhi [MROWS * EMB];
__device__ __nv_bfloat16 g_ylo [MROWS * EMB];
__device__ __nv_bfloat16 g_wbhi[NBIG * EMB];     // [Wq; Wk; Wv] rows
__device__ __nv_bfloat16 g_wblo[NBIG * EMB];
__device__ __nv_bfloat16 g_wphi[EMB * EMB];
__device__ __nv_bfloat16 g_wplo[EMB * EMB];
__device__ __nv_bfloat16 g_kvhi[MROWS * 128];
__device__ __nv_bfloat16 g_kvlo[MROWS * 128];

// ---------------------------------------------------------------------------
// Target-agnostic primitives (valid at .target sm_103)
// ---------------------------------------------------------------------------
__device__ __forceinline__ uint32_t smem_u32(const void* p) {
    uint32_t a;
    asm("{ .reg .u64 t; cvta.to.shared.u64 t, %1; cvt.u32.u64 %0, t; }" : "=r"(a) : "l"(p));
    return a;
}
__device__ __forceinline__ void ldsm_x4(uint32_t& r0, uint32_t& r1,
                                        uint32_t& r2, uint32_t& r3, uint32_t addr)
{
    asm volatile("ldmatrix.sync.aligned.m8n8.x4.shared.b16 {%0,%1,%2,%3}, [%4];"
                 : "=r"(r0), "=r"(r1), "=r"(r2), "=r"(r3) : "r"(addr));
}
__device__ __forceinline__ void ldsm_x4_t(uint32_t& r0, uint32_t& r1,
                                          uint32_t& r2, uint32_t& r3, uint32_t addr)
{
    asm volatile("ldmatrix.sync.aligned.m8n8.x4.trans.shared.b16 {%0,%1,%2,%3}, [%4];"
                 : "=r"(r0), "=r"(r1), "=r"(r2), "=r"(r3) : "r"(addr));
}
__device__ __forceinline__ void mma16816(float* d, const uint32_t* a, const uint32_t* b)
{
    asm volatile("mma.sync.aligned.m16n8k16.row.col.f32.bf16.bf16.f32 "
                 "{%0,%1,%2,%3}, {%4,%5,%6,%7}, {%8,%9}, {%0,%1,%2,%3};"
                 : "+f"(d[0]), "+f"(d[1]), "+f"(d[2]), "+f"(d[3])
                 : "r"(a[0]), "r"(a[1]), "r"(a[2]), "r"(a[3]), "r"(b[0]), "r"(b[1]));
}
__device__ __forceinline__ void cp_async16(uint32_t saddr, const void* gptr) {
    asm volatile("cp.async.cg.shared.global [%0], [%1], 16;" :: "r"(saddr), "l"(gptr));
}
#define CP_COMMIT() asm volatile("cp.async.commit_group;" ::: "memory")
#define CP_WAIT1()  asm volatile("cp.async.wait_group 1;" ::: "memory")

// exp2 on the FMA pipe (no MUFU). Valid for y <= ~1; clamps below -100.
__device__ __forceinline__ float exp2_fast(float y) {
    y = fmaxf(y, -100.f);
    float z = y + 12582912.f;
    int   n = __float_as_int(z) - 0x4B400000;
    float f = y - (z - 12582912.f);
    float p =             1.3333558e-3f;
    p = fmaf(p, f, 9.6181291e-3f);
    p = fmaf(p, f, 5.5504109e-2f);
    p = fmaf(p, f, 2.4022651e-1f);
    p = fmaf(p, f, 6.9314718e-1f);
    p = fmaf(p, f, 1.0f);
    return p * __int_as_float((n + 127) << 23);
}
__device__ __forceinline__ uint32_t pack_bf16(float x, float y) {
    __nv_bfloat162 t = __floats2bfloat162_rn(x, y);
    return *(uint32_t*)&t;
}
__device__ __forceinline__ uint32_t pack_bf16_res(float x, float y, uint32_t hi) {
    __nv_bfloat162 h = *(__nv_bfloat162*)&hi;
    return pack_bf16(x - __bfloat162float(h.x), y - __bfloat162float(h.y));
}

// ---------------------------------------------------------------------------
// Elementwise helpers (round-13 structure: three separate launches)
// ---------------------------------------------------------------------------
__global__ void split_hilo(const float* __restrict__ src,
                           __nv_bfloat16* __restrict__ hi,
                           __nv_bfloat16* __restrict__ lo, int n4)
{
    int i = blockIdx.x * blockDim.x + threadIdx.x;
    if (i >= n4) return;
    float4 v = ((const float4*)src)[i];
    __nv_bfloat16 h0 = __float2bfloat16(v.x), h1 = __float2bfloat16(v.y);
    __nv_bfloat16 h2 = __float2bfloat16(v.z), h3 = __float2bfloat16(v.w);
    __nv_bfloat16 l0 = __float2bfloat16(v.x - __bfloat162float(h0));
    __nv_bfloat16 l1 = __float2bfloat16(v.y - __bfloat162float(h1));
    __nv_bfloat16 l2 = __float2bfloat16(v.z - __bfloat162float(h2));
    __nv_bfloat16 l3 = __float2bfloat16(v.w - __bfloat162float(h3));
    ((__nv_bfloat162*)hi)[2 * i]     = __nv_bfloat162(h0, h1);
    ((__nv_bfloat162*)hi)[2 * i + 1] = __nv_bfloat162(h2, h3);
    ((__nv_bfloat162*)lo)[2 * i]     = __nv_bfloat162(l0, l1);
    ((__nv_bfloat162*)lo)[2 * i + 1] = __nv_bfloat162(l2, l3);
}

// Build [Wq; Wk; Wv] (1152 x 1024) hi/lo in one pass
__global__ void split_wbig(const float* __restrict__ Wq,
                           const float* __restrict__ Wk,
                           const float* __restrict__ Wv)
{
    int i = blockIdx.x * blockDim.x + threadIdx.x;   // 0 .. NBIG*EMB-1
    int j = i >> 10, c = i & 1023;
    float v;
    if (j < 1024)      v = Wq[j * EMB + c];
    else if (j < 1088) v = Wk[(j - 1024) * EMB + c];
    else               v = Wv[(j - 1088) * EMB + c];
    __nv_bfloat16 h = __float2bfloat16(v);
    g_wbhi[i] = h;
    g_wblo[i] = __float2bfloat16(v - __bfloat162float(h));
}

// ---------------------------------------------------------------------------
// hi/lo-aware bf16 split GEMM on mma.sync (round-12, passing at 366.7 total).
// ---------------------------------------------------------------------------
#define NITER  32            // 32 chunks of K=32
#define MATB2  8192          // 128 rows * 64B
#define STAGEB (4 * MATB2)   // Ahi+Alo+Bhi+Blo = 32768
#define GSMEM  (3 * STAGEB)  // 98304

__global__ __launch_bounds__(256, 2)
void gemm3_mma(const __nv_bfloat16* __restrict__ Ahi, const __nv_bfloat16* __restrict__ Alo,
               const __nv_bfloat16* __restrict__ Bhi, const __nv_bfloat16* __restrict__ Blo,
               const float* __restrict__ bias, float* __restrict__ Cf,
               __nv_bfloat16* __restrict__ Chi, __nv_bfloat16* __restrict__ Clo, int ldc,
               __nv_bfloat16* __restrict__ Chi2, __nv_bfloat16* __restrict__ Clo2)
{
    extern __shared__ __align__(16) char sm[];

    const int tid  = threadIdx.x;
    const int wid  = tid >> 5;
    const int lane = tid & 31;
    const int m0 = blockIdx.y * 128;
    const int n0 = blockIdx.x * 128;
    const int wm = (wid & 1) << 6;
    const int wn = (wid >> 1) << 5;

    const int lt = lane >> 3;
    const int lr = lane & 7;
    const int rA = wm + lr + ((lt & 1) << 3);
    const int rB = wn + lr + ((lt >> 1) << 3);
    const uint32_t rowA = (uint32_t)rA * 64;
    const uint32_t rowB = (uint32_t)rB * 64;
    const int rxA = (rA >> 1) & 3;
    const int rxB = (rB >> 1) & 3;
    const int sA  = lt >> 1;
    const int sB  = lt & 1;
    const uint32_t sbase = smem_u32(sm);

    const int lrw0 = tid >> 2,          lsg0 = tid & 3;
    const int lrw1 = (tid + 256) >> 2,  lsg1 = (tid + 256) & 3;
    const uint32_t ldst0 = (uint32_t)lrw0 * 64 + (uint32_t)((lsg0 ^ ((lrw0 >> 1) & 3)) << 4);
    const uint32_t ldst1 = (uint32_t)lrw1 * 64 + (uint32_t)((lsg1 ^ ((lrw1 >> 1) & 3)) << 4);

    float d[4][4][4];
#pragma unroll
    for (int mi = 0; mi < 4; mi++)
#pragma unroll
        for (int ni = 0; ni < 4; ni++)
#pragma unroll
            for (int q = 0; q < 4; q++) d[mi][ni][q] = 0.f;

#define LOAD_STAGE(bufi, ci) do {                                                  \
    const int _k0 = (ci) << 5;                                                     \
    const uint32_t _sb = sbase + (uint32_t)(bufi) * STAGEB;                        \
    cp_async16(_sb + ldst0,             Ahi + (size_t)(m0 + lrw0) * EMB + _k0 + lsg0 * 8); \
    cp_async16(_sb + ldst1,             Ahi + (size_t)(m0 + lrw1) * EMB + _k0 + lsg1 * 8); \
    cp_async16(_sb + MATB2 + ldst0,     Alo + (size_t)(m0 + lrw0) * EMB + _k0 + lsg0 * 8); \
    cp_async16(_sb + MATB2 + ldst1,     Alo + (size_t)(m0 + lrw1) * EMB + _k0 + lsg1 * 8); \
    cp_async16(_sb + 2 * MATB2 + ldst0, Bhi + (size_t)(n0 + lrw0) * EMB + _k0 + lsg0 * 8); \
    cp_async16(_sb + 2 * MATB2 + ldst1, Bhi + (size_t)(n0 + lrw1) * EMB + _k0 + lsg1 * 8); \
    cp_async16(_sb + 3 * MATB2 + ldst0, Blo + (size_t)(n0 + lrw0) * EMB + _k0 + lsg0 * 8); \
    cp_async16(_sb + 3 * MATB2 + ldst1, Blo + (size_t)(n0 + lrw1) * EMB + _k0 + lsg1 * 8); \
} while (0)

    LOAD_STAGE(0, 0); CP_COMMIT();
    LOAD_STAGE(1, 1); CP_COMMIT();

    int buf = 0;
    for (int c = 0; c < NITER; c++) {
        CP_WAIT1();
        __syncthreads();

        if (c + 2 < NITER) LOAD_STAGE((buf + 2) % 3, c + 2);
        CP_COMMIT();

        const uint32_t stb = sbase + (uint32_t)buf * STAGEB;
#pragma unroll
        for (int ks = 0; ks < 2; ks++) {
            const uint32_t aoffk = (uint32_t)(((2 * ks + sA) ^ rxA) << 4);
            const uint32_t boffk = (uint32_t)(((2 * ks + sB) ^ rxB) << 4);

            uint32_t ah[4][4], bh[2][4];
#pragma unroll
            for (int mi = 0; mi < 4; mi++)
                ldsm_x4(ah[mi][0], ah[mi][1], ah[mi][2], ah[mi][3],
                        stb + rowA + (uint32_t)mi * 1024 + aoffk);
#pragma unroll
            for (int nt = 0; nt < 2; nt++)
                ldsm_x4(bh[nt][0], bh[nt][1], bh[nt][2], bh[nt][3],
                        stb + 2 * MATB2 + rowB + (uint32_t)nt * 1024 + boffk);
#pragma unroll
            for (int mi = 0; mi < 4; mi++)
#pragma unroll
                for (int ni = 0; ni < 4; ni++)
                    mma16816(d[mi][ni], ah[mi], &bh[ni >> 1][(ni & 1) * 2]);

            uint32_t bl[2][4];
#pragma unroll
            for (int nt = 0; nt < 2; nt++)
                ldsm_x4(bl[nt][0], bl[nt][1], bl[nt][2], bl[nt][3],
                        stb + 3 * MATB2 + rowB + (uint32_t)nt * 1024 + boffk);
#pragma unroll
            for (int mi = 0; mi < 4; mi++)
#pragma unroll
                for (int ni = 0; ni < 4; ni++)
                    mma16816(d[mi][ni], ah[mi], &bl[ni >> 1][(ni & 1) * 2]);

            uint32_t al[4][4];
#pragma unroll
            for (int mi = 0; mi < 4; mi++)
                ldsm_x4(al[mi][0], al[mi][1], al[mi][2], al[mi][3],
                        stb + MATB2 + rowA + (uint32_t)mi * 1024 + aoffk);
#pragma unroll
            for (int mi = 0; mi < 4; mi++)
#pragma unroll
                for (int ni = 0; ni < 4; ni++)
                    mma16816(d[mi][ni], al[mi], &bh[ni >> 1][(ni & 1) * 2]);
        }
        buf = (buf + 1) % 3;
    }

    __nv_bfloat16* Hi = Chi;
    __nv_bfloat16* Lo = Clo;
    int ld = ldc, cbase = 0;
    if (Chi2 && n0 >= 1024) { Hi = Chi2; Lo = Clo2; ld = 128; cbase = 1024; }

    const int erow = lane >> 2;
    const int ecol = (lane & 3) << 1;
#pragma unroll
    for (int mi = 0; mi < 4; mi++) {
#pragma unroll
        for (int ni = 0; ni < 4; ni++) {
            const int r = m0 + wm + mi * 16 + erow;
            const int cc = n0 + wn + ni * 8 + ecol;
            if (Cf) {
                float bx = 0.f, by = 0.f;
                if (bias) { bx = bias[cc]; by = bias[cc + 1]; }
                *(float2*)(Cf + (size_t)r * ldc + cc) =
                    make_float2(d[mi][ni][0] + bx, d[mi][ni][1] + by);
                *(float2*)(Cf + (size_t)(r + 8) * ldc + cc) =
                    make_float2(d[mi][ni][2] + bx, d[mi][ni][3] + by);
            } else {
                const int co = cc - cbase;
                uint32_t h0 = pack_bf16(d[mi][ni][0], d[mi][ni][1]);
                uint32_t h1 = pack_bf16(d[mi][ni][2], d[mi][ni][3]);
                *(uint32_t*)(Hi + (size_t)r * ld + co) = h0;
                *(uint32_t*)(Hi + (size_t)(r + 8) * ld + co) = h1;
                *(uint32_t*)(Lo + (size_t)r * ld + co) =
                    pack_bf16_res(d[mi][ni][0], d[mi][ni][1], h0);
                *(uint32_t*)(Lo + (size_t)(r + 8) * ld + co) =
                    pack_bf16_res(d[mi][ni][2], d[mi][ni][3], h1);
            }
        }
    }
#undef LOAD_STAGE
}

// ---------------------------------------------------------------------------
// Tensor-core causal MQA flash attention — round-13 shape verbatim:
// packed 128B rows + SW128 swizzle, 2 CTAs/SM, k-major S with fragment reuse.
// smem: qhi @0 (16384), qlo @16384 | stages @32768, 32768 each:
//       khi@0, klo@8192, vhi@16384, vlo@24576
// ---------------------------------------------------------------------------
#define SM_QLO2 16384
#define SM_KV2  32768
#define STG2    32768
#define ATT_SMEM (SM_KV2 + 2 * STG2)   // 98304

__global__ __launch_bounds__(128, 2)
void mqa_attn_mma(const __nv_bfloat16* __restrict__ qhi,
                  const __nv_bfloat16* __restrict__ qlo,
                  const __nv_bfloat16* __restrict__ kvhi,
                  const __nv_bfloat16* __restrict__ kvlo,
                  __nv_bfloat16* __restrict__ yhi,
                  __nv_bfloat16* __restrict__ ylo)
{
    extern __shared__ __align__(16) char sm[];
    const int qt   = (int)gridDim.x - 1 - (int)blockIdx.x;  // big tiles first
    const int h    = blockIdx.y;
    const int b    = blockIdx.z;
    const int tid  = threadIdx.x;
    const int w    = tid >> 5;
    const int lane = tid & 31;
    const uint32_t sbase = smem_u32(sm);

    const int lt = lane >> 3;
    const int lr = lane & 7;
    const uint32_t qrow = (uint32_t)(32 * w + lr + ((lt & 1) << 3)) * 128;  // + mi*2048
    const int sQ = lt >> 1;
    const uint32_t krow = (uint32_t)(lr + ((lt >> 1) << 3)) * 128;          // + n2*2048
    const int sK = lt & 1;
    const uint32_t vrow = (uint32_t)(lr + ((lt & 1) << 3)) * 128;           // + ks*2048
    const int sV = lt >> 1;

    // ---- load Q tile (contiguous 8 q_raw rows = [128,64]) into smem hi/lo ----
    {
        size_t qoff = ((size_t)b * SEQ + (size_t)(h * 128 + qt * 8)) * EMB;
        const uint4* sh = (const uint4*)(qhi + qoff);
        const uint4* sl = (const uint4*)(qlo + qoff);
#pragma unroll
        for (int i = 0; i < 8; i++) {
            int c = tid + i * 128;          // 0..1023 chunks of 16B
            int r = c >> 3, sg = c & 7;
            uint32_t dst = (uint32_t)r * 128 + (uint32_t)((sg ^ (r & 7)) << 4);
            *(uint4*)(sm + dst)            = sh[c];
            *(uint4*)(sm + SM_QLO2 + dst)  = sl[c];
        }
    }

#define LOAD_KV(bufi, s) do {                                                      \
    size_t _rb = ((size_t)b * SEQ + (size_t)(s) * 64) * 128;                       \
    const char* _sh = (const char*)(kvhi + _rb);                                   \
    const char* _sl = (const char*)(kvlo + _rb);                                   \
    uint32_t _sb = sbase + SM_KV2 + (uint32_t)(bufi) * STG2;                       \
    _Pragma("unroll")                                                              \
    for (int _i = 0; _i < 8; _i++) {                                               \
        int _c = tid + _i * 128;                                                   \
        int _r = _c >> 4, _sg = _c & 15;                                           \
        uint32_t _dst = ((_sg < 8) ? 0u : 16384u)                                  \
                      + (uint32_t)_r * 128                                         \
                      + (uint32_t)((( _sg & 7) ^ (_r & 7)) << 4);                  \
        cp_async16(_sb + _dst,         _sh + _r * 256 + _sg * 16);                 \
        cp_async16(_sb + _dst + 8192,  _sl + _r * 256 + _sg * 16);                 \
    }                                                                              \
} while (0)

    float O[2][8][4];
#pragma unroll
    for (int mi = 0; mi < 2; mi++)
#pragma unroll
        for (int nt = 0; nt < 8; nt++)
#pragma unroll
            for (int q = 0; q < 4; q++) O[mi][nt][q] = 0.f;
    float mrow[2][2] = {{-1e30f, -1e30f}, {-1e30f, -1e30f}};
    float lrow[2][2] = {{0.f, 0.f}, {0.f, 0.f}};

    const float QSC = 0.125f * 1.44269504088896340736f;
    const int ntl = 2 * qt + 2;

    LOAD_KV(0, 0); CP_COMMIT();

    for (int s = 0; s < ntl; s++) {
        __syncthreads();                       // everyone done reading buf (s+1)&1
        if (s + 1 < ntl) LOAD_KV((s + 1) & 1, s + 1);
        CP_COMMIT();
        CP_WAIT1();                            // stage s complete
        __syncthreads();

        const uint32_t kb = sbase + SM_KV2 + (uint32_t)(s & 1) * STG2;

        // ---- S = Qhi@Khi + Qhi@Klo + Qlo@Khi (k-major, fragment reuse) ----
        float S[2][8][4];
#pragma unroll
        for (int mi = 0; mi < 2; mi++)
#pragma unroll
            for (int nt = 0; nt < 8; nt++)
#pragma unroll
                for (int q = 0; q < 4; q++) S[mi][nt][q] = 0.f;

#pragma unroll
        for (int ks = 0; ks < 4; ks++) {
            const uint32_t qoffk = (uint32_t)(((2 * ks + sQ) ^ lr) << 4);
            const uint32_t koffk = (uint32_t)(((2 * ks + sK) ^ lr) << 4);

            uint32_t qh[2][4], kh[4][4];
#pragma unroll
            for (int mi = 0; mi < 2; mi++)
                ldsm_x4(qh[mi][0], qh[mi][1], qh[mi][2], qh[mi][3],
                        sbase + qrow + (uint32_t)mi * 2048 + qoffk);
#pragma unroll
            for (int n2 = 0; n2 < 4; n2++)
                ldsm_x4(kh[n2][0], kh[n2][1], kh[n2][2], kh[n2][3],
                        kb + krow + (uint32_t)n2 * 2048 + koffk);
#pragma unroll
            for (int mi = 0; mi < 2; mi++)
#pragma unroll
                for (int nt = 0; nt < 8; nt++)
                    mma16816(S[mi][nt], qh[mi], &kh[nt >> 1][(nt & 1) * 2]);

            uint32_t kl[4][4];
#pragma unroll
            for (int n2 = 0; n2 < 4; n2++)
                ldsm_x4(kl[n2][0], kl[n2][1], kl[n2][2], kl[n2][3],
                        kb + 8192u + krow + (uint32_t)n2 * 2048 + koffk);
#pragma unroll
            for (int mi = 0; mi < 2; mi++)
#pragma unroll
                for (int nt = 0; nt < 8; nt++)
                    mma16816(S[mi][nt], qh[mi], &kl[nt >> 1][(nt & 1) * 2]);

            uint32_t ql[2][4];
#pragma unroll
            for (int mi = 0; mi < 2; mi++)
                ldsm_x4(ql[mi][0], ql[mi][1], ql[mi][2], ql[mi][3],
                        sbase + SM_QLO2 + qrow + (uint32_t)mi * 2048 + qoffk);
#pragma unroll
            for (int mi = 0; mi < 2; mi++)
#pragma unroll
                for (int nt = 0; nt < 8; nt++)
                    mma16816(S[mi][nt], ql[mi], &kh[nt >> 1][(nt & 1) * 2]);
        }

        // ---- mask (diagonal tiles only) + scale ----
        if (s >= 2 * qt) {
#pragma unroll
            for (int mi = 0; mi < 2; mi++) {
                const int r0 = qt * 128 + 32 * w + 16 * mi + (lane >> 2);
#pragma unroll
                for (int nt = 0; nt < 8; nt++) {
                    const int jb = s * 64 + nt * 8 + 2 * (lane & 3);
                    if (jb     > r0)     S[mi][nt][0] = -1e30f;
                    if (jb + 1 > r0)     S[mi][nt][1] = -1e30f;
                    if (jb     > r0 + 8) S[mi][nt][2] = -1e30f;
                    if (jb + 1 > r0 + 8) S[mi][nt][3] = -1e30f;
                }
            }
        }
#pragma unroll
        for (int mi = 0; mi < 2; mi++)
#pragma unroll
            for (int nt = 0; nt < 8; nt++)
#pragma unroll
                for (int q = 0; q < 4; q++) S[mi][nt][q] *= QSC;

        // ---- online softmax on fragments ----
        uint32_t phi[2][4][4], plo[2][4][4];
#pragma unroll
        for (int mi = 0; mi < 2; mi++) {
            float t0 = -1e30f, t1 = -1e30f;
#pragma unroll
            for (int nt = 0; nt < 8; nt++) {
                t0 = fmaxf(t0, fmaxf(S[mi][nt][0], S[mi][nt][1]));
                t1 = fmaxf(t1, fmaxf(S[mi][nt][2], S[mi][nt][3]));
            }
            t0 = fmaxf(t0, __shfl_xor_sync(0xffffffffu, t0, 1));
            t0 = fmaxf(t0, __shfl_xor_sync(0xffffffffu, t0, 2));
            t1 = fmaxf(t1, __shfl_xor_sync(0xffffffffu, t1, 1));
            t1 = fmaxf(t1, __shfl_xor_sync(0xffffffffu, t1, 2));
            const float m0n = fmaxf(mrow[mi][0], t0);
            const float m1n = fmaxf(mrow[mi][1], t1);
            const float c0 = exp2_fast(mrow[mi][0] - m0n);
            const float c1 = exp2_fast(mrow[mi][1] - m1n);
            mrow[mi][0] = m0n; mrow[mi][1] = m1n;
            lrow[mi][0] *= c0; lrow[mi][1] *= c1;
#pragma unroll
            for (int nt = 0; nt < 8; nt++) {
                O[mi][nt][0] *= c0; O[mi][nt][1] *= c0;
                O[mi][nt][2] *= c1; O[mi][nt][3] *= c1;
            }
            float ps0 = 0.f, ps1 = 0.f;
#pragma unroll
            for (int nt = 0; nt < 8; nt++) {
                float p0 = exp2_fast(S[mi][nt][0] - m0n);
                float p1 = exp2_fast(S[mi][nt][1] - m0n);
                float p2 = exp2_fast(S[mi][nt][2] - m1n);
                float p3 = exp2_fast(S[mi][nt][3] - m1n);
                ps0 += p0 + p1; ps1 += p2 + p3;
                S[mi][nt][0] = p0; S[mi][nt][1] = p1;
                S[mi][nt][2] = p2; S[mi][nt][3] = p3;
            }
            lrow[mi][0] += ps0; lrow[mi][1] += ps1;
            // pack P -> bf16 hi/lo A-fragments (C layout == A layout)
#pragma unroll
            for (int ks = 0; ks < 4; ks++) {
                phi[mi][ks][0] = pack_bf16(S[mi][2*ks][0],   S[mi][2*ks][1]);
                phi[mi][ks][1] = pack_bf16(S[mi][2*ks][2],   S[mi][2*ks][3]);
                phi[mi][ks][2] = pack_bf16(S[mi][2*ks+1][0], S[mi][2*ks+1][1]);
                phi[mi][ks][3] = pack_bf16(S[mi][2*ks+1][2], S[mi][2*ks+1][3]);
                plo[mi][ks][0] = pack_bf16_res(S[mi][2*ks][0],   S[mi][2*ks][1],   phi[mi][ks][0]);
                plo[mi][ks][1] = pack_bf16_res(S[mi][2*ks][2],   S[mi][2*ks][3],   phi[mi][ks][1]);
                plo[mi][ks][2] = pack_bf16_res(S[mi][2*ks+1][0], S[mi][2*ks+1][1], phi[mi][ks][2]);
                plo[mi][ks][3] = pack_bf16_res(S[mi][2*ks+1][2], S[mi][2*ks+1][3], phi[mi][ks][3]);
            }
        }

        // ---- O += Phi@Vhi + Plo@Vhi + Phi@Vlo (fragment reuse) ----
#pragma unroll
        for (int ks = 0; ks < 4; ks++) {
            const uint32_t vrb = vrow + (uint32_t)ks * 2048;
            uint32_t vh[4][4];
#pragma unroll
            for (int ng = 0; ng < 4; ng++)
                ldsm_x4_t(vh[ng][0], vh[ng][1], vh[ng][2], vh[ng][3],
                          kb + 16384u + vrb + (uint32_t)(((2 * ng + sV) ^ lr) << 4));
#pragma unroll
            for (int mi = 0; mi < 2; mi++)
#pragma unroll
                for (int nt = 0; nt < 8; nt++) {
                    const uint32_t* bb = &vh[nt >> 1][(nt & 1) * 2];
                    mma16816(O[mi][nt], phi[mi][ks], bb);
                    mma16816(O[mi][nt], plo[mi][ks], bb);
                }
            uint32_t vl[4][4];
#pragma unroll
            for (int ng = 0; ng < 4; ng++)
                ldsm_x4_t(vl[ng][0], vl[ng][1], vl[ng][2], vl[ng][3],
                          kb + 24576u + vrb + (uint32_t)(((2 * ng + sV) ^ lr) << 4));
#pragma unroll
            for (int mi = 0; mi < 2; mi++)
#pragma unroll
                for (int nt = 0; nt < 8; nt++)
                    mma16816(O[mi][nt], phi[mi][ks], &vl[nt >> 1][(nt & 1) * 2]);
        }
    }

    // ---- finalize: quad-reduce l, normalize, store bf16 hi/lo ----
#pragma unroll
    for (int mi = 0; mi < 2; mi++) {
        float l0 = lrow[mi][0], l1 = lrow[mi][1];
        l0 += __shfl_xor_sync(0xffffffffu, l0, 1);
        l0 += __shfl_xor_sync(0xffffffffu, l0, 2);
        l1 += __shfl_xor_sync(0xffffffffu, l1, 1);
        l1 += __shfl_xor_sync(0xffffffffu, l1, 2);
        const float i0 = 1.f / l0, i1 = 1.f / l1;
        const int r0 = qt * 128 + 32 * w + 16 * mi + (lane >> 2);
#pragma unroll
        for (int nt = 0; nt < 8; nt++) {
            const int col = h * HS + nt * 8 + 2 * (lane & 3);
            const size_t i0x = ((size_t)b * SEQ + r0) * EMB + col;
            const size_t i1x = ((size_t)b * SEQ + r0 + 8) * EMB + col;
            float v0 = O[mi][nt][0] * i0, v1 = O[mi][nt][1] * i0;
            float v2 = O[mi][nt][2] * i1, v3 = O[mi][nt][3] * i1;
            uint32_t ph0 = pack_bf16(v0, v1), ph1 = pack_bf16(v2, v3);
            *(uint32_t*)(yhi + i0x) = ph0;
            *(uint32_t*)(yhi + i1x) = ph1;
            *(uint32_t*)(ylo + i0x) = pack_bf16_res(v0, v1, ph0);
            *(uint32_t*)(ylo + i1x) = pack_bf16_res(v2, v3, ph1);
        }
    }
#undef LOAD_KV
}

// ---------------------------------------------------------------------------
extern "C" void kernel_launch(void* const* d_in, const int* in_sizes, int n_in,
                              void* d_out, int out_size)
{
    const float* x  = (const float*)d_in[0];
    const float* Wk = (const float*)d_in[1];
    const float* Wv = (const float*)d_in[2];
    const float* Wq = (const float*)d_in[3];
    const float* Wp = (const float*)d_in[4];
    const float* bp = (const float*)d_in[5];
    float* out = (float*)d_out;

    __nv_bfloat16 *xhi, *xlo, *qhi, *qlo, *yhi, *ylo;
    __nv_bfloat16 *wbhi, *wblo, *wphi, *wplo, *kvhi, *kvlo;
    cudaGetSymbolAddress((void**)&xhi, g_xhi);   cudaGetSymbolAddress((void**)&xlo, g_xlo);
    cudaGetSymbolAddress((void**)&qhi, g_qhi);   cudaGetSymbolAddress((void**)&qlo, g_qlo);
    cudaGetSymbolAddress((void**)&yhi, g_yhi);   cudaGetSymbolAddress((void**)&ylo, g_ylo);
    cudaGetSymbolAddress((void**)&wbhi, g_wbhi); cudaGetSymbolAddress((void**)&wblo, g_wblo);
    cudaGetSymbolAddress((void**)&wphi, g_wphi); cudaGetSymbolAddress((void**)&wplo, g_wplo);
    cudaGetSymbolAddress((void**)&kvhi, g_kvhi); cudaGetSymbolAddress((void**)&kvlo, g_kvlo);

    cudaFuncSetAttribute(gemm3_mma, cudaFuncAttributeMaxDynamicSharedMemorySize, GSMEM);
    cudaFuncSetAttribute(mqa_attn_mma, cudaFuncAttributeMaxDynamicSharedMemorySize, ATT_SMEM);

    // precision splits (inputs only) — round-13 structure
    split_wbig<<<NBIG * EMB / 256, 256>>>(Wq, Wk, Wv);
    split_hilo<<<(MROWS * EMB / 4 + 255) / 256, 256>>>(x,  xhi, xlo, MROWS * EMB / 4);
    split_hilo<<<(EMB * EMB / 4 + 255) / 256, 256>>>(Wp, wphi, wplo, EMB * EMB / 4);

    // [q | kv] = x @ [Wq;Wk;Wv]^T -> q bf16 hi/lo [4096,1024] + kv hi/lo [4096,128]
    gemm3_mma<<<dim3(NBIG / 128, MROWS / 128), 256, GSMEM>>>(
        xhi, xlo, wbhi, wblo, nullptr, nullptr,
        qhi, qlo, EMB, kvhi, kvlo);

    // tensor-core flash attention (1 head/block, 512 blocks, 2 CTA/SM) -> y hi/lo
    mqa_attn_mma<<<dim3(SEQ / 128, NHEAD, BATCH), 128, ATT_SMEM>>>(
        qhi, qlo, kvhi, kvlo, yhi, ylo);

    // out = y @ Wp^T + bp (fp32 out)
    gemm3_mma<<<dim3(EMB / 128, MROWS / 128), 256, GSMEM>>>(
        yhi, ylo, wphi, wplo, bp, out, nullptr, nullptr, EMB,
        nullptr, nullptr);
}